// round 4
// baseline (speedup 1.0000x reference)
#include <cuda_runtime.h>

// ---------------------------------------------------------------------------
// GCN: 3 layers, symmetric normalization with self-loops.
//   out = A ReLU(A ReLU(A x W1 + b1) W2 + b2) W3 + b3,  A = D^-1/2 (Adj+I) D^-1/2
// Layer1 computes (A x) W1 (aggregate at F=64), layer3 computes A (h W3)
// (aggregate at F=64). Layer2 aggregates at F=128.
//
// edge_index is int32 (JAX default config downcasts the reference's int64).
// All scratch in __device__ globals (16B aligned); buffer binding is a
// compile-time template parameter so no runtime address-space selects.
// ---------------------------------------------------------------------------

#define NODES 100000
#define EDGES 1600000

__device__ __align__(16) float g_deg [NODES];
__device__ __align__(16) float g_dinv[NODES];
__device__ __align__(16) int   g_src [EDGES];
__device__ __align__(16) int   g_dst [EDGES];
__device__ __align__(16) float g_coef[EDGES];
__device__ __align__(16) float g_buf1[(size_t)NODES * 128];
__device__ __align__(16) float g_buf2[(size_t)NODES * 128];

// Compile-time buffer binding: SEL 0 = external param pointer, 1/2 = globals.
template <int SEL>
__device__ __forceinline__ const float* cbuf(const float* ext) {
    if constexpr (SEL == 1) return g_buf1;
    else if constexpr (SEL == 2) return g_buf2;
    else return ext;
}
template <int SEL>
__device__ __forceinline__ float* mbuf(float* ext) {
    if constexpr (SEL == 1) return g_buf1;
    else if constexpr (SEL == 2) return g_buf2;
    else return ext;
}

// ---------------------------------------------------------------------------
__global__ void deg_init_kernel(int n) {
    int i = blockIdx.x * blockDim.x + threadIdx.x;
    if (i < n) g_deg[i] = 1.0f;  // self-loop
}

__global__ void deg_count_kernel(const int* __restrict__ ei, int e) {
    int i = blockIdx.x * blockDim.x + threadIdx.x;
    if (i < e) atomicAdd(&g_deg[ei[e + i]], 1.0f);
}

__global__ void dinv_kernel(int n) {
    int i = blockIdx.x * blockDim.x + threadIdx.x;
    if (i < n) g_dinv[i] = rsqrtf(g_deg[i]);  // deg >= 1 (self-loop)
}

// Copy indices and precompute per-edge coefficient.
__global__ void edge_prep_kernel(const int* __restrict__ ei, int e) {
    int i = blockIdx.x * blockDim.x + threadIdx.x;
    if (i < e) {
        int s = ei[i];
        int d = ei[e + i];
        g_src[i] = s;
        g_dst[i] = d;
        g_coef[i] = g_dinv[s] * g_dinv[d];
    }
}

// out[i,:] = h[i,:] * dinv[i]^2   (self-loop contribution; initializes out)
template <int F, int HSEL, int OSEL>
__global__ void agg_self_kernel(const float* h_ext, float* out_ext, int n) {
    const float* __restrict__ h = cbuf<HSEL>(h_ext);
    float* __restrict__ out = mbuf<OSEL>(out_ext);
    const int CH = F / 4;
    int t = blockIdx.x * blockDim.x + threadIdx.x;
    if (t >= n * CH) return;
    int i = t / CH, q = t % CH;
    float c = g_dinv[i]; c = c * c;
    float4 v = *(const float4*)(h + (size_t)i * F + q * 4);
    v.x *= c; v.y *= c; v.z *= c; v.w *= c;
    *(float4*)(out + (size_t)i * F + q * 4) = v;
}

// out[dst,:] += h[src,:] * coef   (scatter-add over edges)
template <int F, int HSEL, int OSEL>
__global__ void agg_edge_kernel(const float* h_ext, float* out_ext, int e) {
    const float* __restrict__ h = cbuf<HSEL>(h_ext);
    float* out = mbuf<OSEL>(out_ext);
    const int CH = F / 4;
    int t = blockIdx.x * blockDim.x + threadIdx.x;
    if (t >= e * CH) return;
    int ed = t / CH, q = t % CH;
    int s = g_src[ed], d = g_dst[ed];
    float c = g_coef[ed];
    float4 v = *(const float4*)(h + (size_t)s * F + q * 4);
    float* o = out + (size_t)d * F + q * 4;
    atomicAdd(o + 0, v.x * c);
    atomicAdd(o + 1, v.y * c);
    atomicAdd(o + 2, v.z * c);
    atomicAdd(o + 3, v.w * c);
}

// ---------------------------------------------------------------------------
// Tiled SGEMM: C[n,NOUT] = A[n,K] @ W[K,NOUT] (+bias) (+relu)
// 64x64 block tile, BK=32, 256 threads, 4x4 microtile.
// ---------------------------------------------------------------------------
template <int K, int NOUT, bool RELU, bool BIAS, int ASEL, int CSEL>
__global__ void gemm_kernel(const float* A_ext,
                            const float* __restrict__ W,
                            const float* __restrict__ bias,
                            float* C_ext, int n) {
    const float* __restrict__ A = cbuf<ASEL>(A_ext);
    float* __restrict__ C = mbuf<CSEL>(C_ext);

    __shared__ float As[32][68];   // [k][m], padded
    __shared__ float Bs[32][64];   // [k][c]

    const int tid = threadIdx.x;
    const int tx = tid % 16;       // column group
    const int ty = tid / 16;       // row group
    const int rowBase = blockIdx.y * 64;
    const int colBase = blockIdx.x * 64;

    float acc[4][4];
#pragma unroll
    for (int i = 0; i < 4; i++)
#pragma unroll
        for (int j = 0; j < 4; j++) acc[i][j] = 0.0f;

    for (int ks = 0; ks < K; ks += 32) {
        // A tile: 64 rows x 32 k -> 512 float4, 2 per thread, store transposed
#pragma unroll
        for (int l = 0; l < 2; l++) {
            int f = tid + l * 256;          // [0,512)
            int row = f / 8;                // 8 float4 per row
            int kq = f % 8;
            int rg = rowBase + row;
            float4 v = make_float4(0.f, 0.f, 0.f, 0.f);
            if (rg < n) v = *(const float4*)(A + (size_t)rg * K + ks + kq * 4);
            As[kq * 4 + 0][row] = v.x;
            As[kq * 4 + 1][row] = v.y;
            As[kq * 4 + 2][row] = v.z;
            As[kq * 4 + 3][row] = v.w;
        }
        // B tile: 32 k x 64 cols -> 512 float4, 2 per thread
#pragma unroll
        for (int l = 0; l < 2; l++) {
            int f = tid + l * 256;
            int k = f / 16;                 // 16 float4 per row
            int cq = f % 16;
            float4 v = *(const float4*)(W + (size_t)(ks + k) * NOUT + colBase + cq * 4);
            *(float4*)&Bs[k][cq * 4] = v;
        }
        __syncthreads();

#pragma unroll
        for (int k = 0; k < 32; k++) {
            float4 a4 = *(const float4*)&As[k][ty * 4];
            float4 b4 = *(const float4*)&Bs[k][tx * 4];
            float a[4] = {a4.x, a4.y, a4.z, a4.w};
            float b[4] = {b4.x, b4.y, b4.z, b4.w};
#pragma unroll
            for (int i = 0; i < 4; i++)
#pragma unroll
                for (int j = 0; j < 4; j++) acc[i][j] += a[i] * b[j];
        }
        __syncthreads();
    }

#pragma unroll
    for (int i = 0; i < 4; i++) {
        int row = rowBase + ty * 4 + i;
        if (row >= n) continue;
#pragma unroll
        for (int j = 0; j < 4; j++) {
            int col = colBase + tx * 4 + j;
            float v = acc[i][j];
            if (BIAS) v += bias[col];
            if (RELU) v = fmaxf(v, 0.0f);
            C[(size_t)row * NOUT + col] = v;
        }
    }
}

__global__ void bias_add_kernel(float* __restrict__ out,
                                const float* __restrict__ b, int n) {
    int t = blockIdx.x * blockDim.x + threadIdx.x;
    if (t < n * 64) out[t] += b[t % 64];
}

// ---------------------------------------------------------------------------
extern "C" void kernel_launch(void* const* d_in, const int* in_sizes, int n_in,
                              void* d_out, int out_size) {
    const float* x   = (const float*)d_in[0];
    const int*   ei  = (const int*)d_in[1];     // int32 (JAX default x64-off)
    const float* W1  = (const float*)d_in[2];
    const float* b1  = (const float*)d_in[3];
    const float* W2  = (const float*)d_in[4];
    const float* b2  = (const float*)d_in[5];
    const float* W3  = (const float*)d_in[6];
    const float* b3  = (const float*)d_in[7];
    float* out = (float*)d_out;

    const int N = in_sizes[0] / 64;
    const int E = in_sizes[1] / 2;

    const int T = 256;
    auto blk = [&](long long w) { return (int)((w + T - 1) / T); };

    // degree + norm
    deg_init_kernel<<<blk(N), T>>>(N);
    deg_count_kernel<<<blk(E), T>>>(ei, E);
    dinv_kernel<<<blk(N), T>>>(N);
    edge_prep_kernel<<<blk(E), T>>>(ei, E);

    // Layer 1: y = A x (F=64) into buf1; h1 = relu(y @ W1 + b1) into buf2
    agg_self_kernel<64, 0, 1><<<blk((long long)N * 16), T>>>(x, nullptr, N);
    agg_edge_kernel<64, 0, 1><<<blk((long long)E * 16), T>>>(x, nullptr, E);
    {
        dim3 grid(2, (N + 63) / 64);
        gemm_kernel<64, 128, true, true, 1, 2><<<grid, 256>>>(nullptr, W1, b1, nullptr, N);
    }

    // Layer 2: z = A h1 (F=128) into buf1; h2 = relu(z @ W2 + b2) into buf2
    agg_self_kernel<128, 2, 1><<<blk((long long)N * 32), T>>>(nullptr, nullptr, N);
    agg_edge_kernel<128, 2, 1><<<blk((long long)E * 32), T>>>(nullptr, nullptr, E);
    {
        dim3 grid(2, (N + 63) / 64);
        gemm_kernel<128, 128, true, true, 1, 2><<<grid, 256>>>(nullptr, W2, b2, nullptr, N);
    }

    // Layer 3: hw = h2 @ W3 (no bias) into buf1; out = A hw + b3 (F=64)
    {
        dim3 grid(1, (N + 63) / 64);
        gemm_kernel<128, 64, false, false, 2, 1><<<grid, 256>>>(nullptr, W3, nullptr, nullptr, N);
    }
    agg_self_kernel<64, 1, 0><<<blk((long long)N * 16), T>>>(nullptr, out, N);
    agg_edge_kernel<64, 1, 0><<<blk((long long)E * 16), T>>>(nullptr, out, E);
    bias_add_kernel<<<blk((long long)N * 16), T>>>(out, b3, N);
}

// round 5
// speedup vs baseline: 2.8037x; 2.8037x over previous
#include <cuda_runtime.h>

// ---------------------------------------------------------------------------
// GCN, 3 layers, A = D^-1/2 (Adj+I) D^-1/2.
// Aggregation is PULL-based over a CSR built per call (no float atomics):
//   out[i] = dinv[i] * ( sum_{e in(i)} hs[col[e]] + hs[i] ),  hs = h * dinv[row]
// The dinv[src] pre-scale is fused into the previous GEMM epilogue; the
// dinv[dst] post-scale (and final bias) is fused into the gather.
// Layer1 aggregates x at F=64, layer3 aggregates (h2 W3) at F=64.
// ---------------------------------------------------------------------------

#define NODES 100000
#define EDGES 1600000
#define SCAN_BS 1024

__device__ __align__(16) int   g_cnt   [NODES];
__device__ __align__(16) int   g_rowptr[NODES + 1];
__device__ __align__(16) int   g_cursor[NODES];
__device__ __align__(16) int   g_blocksum[(NODES + SCAN_BS - 1) / SCAN_BS + 1];
__device__ __align__(16) float g_dinv  [NODES];
__device__ __align__(16) int   g_col   [EDGES];
__device__ __align__(16) float g_buf1[(size_t)NODES * 128];
__device__ __align__(16) float g_buf2[(size_t)NODES * 128];

// Compile-time buffer binding (no runtime address-space selects).
template <int SEL>
__device__ __forceinline__ const float* cbuf(const float* ext) {
    if constexpr (SEL == 1) return g_buf1;
    else if constexpr (SEL == 2) return g_buf2;
    else return ext;
}
template <int SEL>
__device__ __forceinline__ float* mbuf(float* ext) {
    if constexpr (SEL == 1) return g_buf1;
    else if constexpr (SEL == 2) return g_buf2;
    else return ext;
}

// --------------------------- CSR construction ------------------------------
__global__ void cnt_zero_kernel(int n) {
    int i = blockIdx.x * blockDim.x + threadIdx.x;
    if (i < n) g_cnt[i] = 0;
}

__global__ void cnt_count_kernel(const int* __restrict__ ei, int e) {
    int i = blockIdx.x * blockDim.x + threadIdx.x;
    if (i < e) atomicAdd(&g_cnt[ei[e + i]], 1);
}

__global__ void dinv_kernel(int n) {
    int i = blockIdx.x * blockDim.x + threadIdx.x;
    if (i < n) g_dinv[i] = rsqrtf((float)(g_cnt[i] + 1));  // +1 self-loop
}

// Inclusive scan of g_cnt into g_rowptr[1..n], per-block partials + blocksums.
__global__ void scan1_kernel(int n) {
    __shared__ int sh[SCAN_BS];
    int i = blockIdx.x * SCAN_BS + threadIdx.x;
    int v = (i < n) ? g_cnt[i] : 0;
    sh[threadIdx.x] = v;
    __syncthreads();
#pragma unroll
    for (int off = 1; off < SCAN_BS; off <<= 1) {
        int t = (threadIdx.x >= off) ? sh[threadIdx.x - off] : 0;
        __syncthreads();
        sh[threadIdx.x] += t;
        __syncthreads();
    }
    if (i < n) g_rowptr[i + 1] = sh[threadIdx.x];
    if (threadIdx.x == SCAN_BS - 1) g_blocksum[blockIdx.x] = sh[threadIdx.x];
}

__global__ void scan2_kernel(int nb) {  // serial exclusive scan of block sums
    if (threadIdx.x == 0 && blockIdx.x == 0) {
        int run = 0;
        for (int b = 0; b < nb; b++) { int v = g_blocksum[b]; g_blocksum[b] = run; run += v; }
    }
}

__global__ void scan3_kernel(int n) {
    int i = blockIdx.x * blockDim.x + threadIdx.x;
    if (i < n) g_rowptr[i + 1] += g_blocksum[i / SCAN_BS];
    if (i == 0) g_rowptr[0] = 0;
}

__global__ void cursor_init_kernel(int n) {
    int i = blockIdx.x * blockDim.x + threadIdx.x;
    if (i < n) g_cursor[i] = g_rowptr[i];
}

__global__ void csr_fill_kernel(const int* __restrict__ ei, int e) {
    int i = blockIdx.x * blockDim.x + threadIdx.x;
    if (i < e) {
        int s = ei[i];
        int d = ei[e + i];
        int pos = atomicAdd(&g_cursor[d], 1);
        g_col[pos] = s;
    }
}

// --------------------------- feature kernels -------------------------------
// xs[i,:] = x[i,:] * dinv[i]   (layer-1 input pre-scale)
__global__ void scale_x_kernel(const float* __restrict__ x, int n) {
    int t = blockIdx.x * blockDim.x + threadIdx.x;
    if (t >= n * 16) return;
    int i = t / 16, q = t % 16;
    float dv = g_dinv[i];
    float4 v = *(const float4*)(x + (size_t)i * 64 + q * 4);
    v.x *= dv; v.y *= dv; v.z *= dv; v.w *= dv;
    *(float4*)(g_buf1 + (size_t)i * 64 + q * 4) = v;
}

// Pull aggregation: one warp per node; lanes own feature slices.
// out[i,:] = dinv[i] * ( sum_{e} hs[col[e],:] + hs[i,:] )  (+ bias)
template <int F, int HSEL, int OSEL, bool BIAS>
__global__ void gather_kernel(const float* h_ext, float* out_ext,
                              const float* __restrict__ bias, int n) {
    const float* __restrict__ hs = cbuf<HSEL>(h_ext);
    float* __restrict__ out = mbuf<OSEL>(out_ext);
    int warp = (blockIdx.x * blockDim.x + threadIdx.x) >> 5;
    int lane = threadIdx.x & 31;
    if (warp >= n) return;
    int beg = g_rowptr[warp], end = g_rowptr[warp + 1];

    if constexpr (F == 64) {
        float2 acc = *(const float2*)(hs + (size_t)warp * 64 + lane * 2);  // self
        for (int base = beg; base < end; base += 32) {
            int e = base + lane;
            int c = (e < end) ? g_col[e] : 0;
            int m = min(32, end - base);
            for (int j = 0; j < m; j++) {
                int s = __shfl_sync(0xffffffffu, c, j);
                float2 v = *(const float2*)(hs + (size_t)s * 64 + lane * 2);
                acc.x += v.x; acc.y += v.y;
            }
        }
        float dv = g_dinv[warp];
        acc.x *= dv; acc.y *= dv;
        if constexpr (BIAS) { acc.x += bias[lane * 2]; acc.y += bias[lane * 2 + 1]; }
        *(float2*)(out + (size_t)warp * 64 + lane * 2) = acc;
    } else {  // F == 128
        float4 acc = *(const float4*)(hs + (size_t)warp * 128 + lane * 4);  // self
        for (int base = beg; base < end; base += 32) {
            int e = base + lane;
            int c = (e < end) ? g_col[e] : 0;
            int m = min(32, end - base);
            for (int j = 0; j < m; j++) {
                int s = __shfl_sync(0xffffffffu, c, j);
                float4 v = *(const float4*)(hs + (size_t)s * 128 + lane * 4);
                acc.x += v.x; acc.y += v.y; acc.z += v.z; acc.w += v.w;
            }
        }
        float dv = g_dinv[warp];
        acc.x *= dv; acc.y *= dv; acc.z *= dv; acc.w *= dv;
        *(float4*)(out + (size_t)warp * 128 + lane * 4) = acc;
    }
}

// ---------------------------------------------------------------------------
// Tiled SGEMM: C[n,NOUT] = A[n,K] @ W[K,NOUT] (+bias)(+relu)(*dinv[row])
// 64x64 block tile, BK=32, 256 threads, 4x4 microtile.
// ---------------------------------------------------------------------------
template <int K, int NOUT, bool RELU, bool BIAS, bool SCALE, int ASEL, int CSEL>
__global__ void gemm_kernel(const float* A_ext,
                            const float* __restrict__ W,
                            const float* __restrict__ bias,
                            float* C_ext, int n) {
    const float* __restrict__ A = cbuf<ASEL>(A_ext);
    float* __restrict__ C = mbuf<CSEL>(C_ext);

    __shared__ float As[32][68];
    __shared__ float Bs[32][64];

    const int tid = threadIdx.x;
    const int tx = tid % 16;
    const int ty = tid / 16;
    const int rowBase = blockIdx.y * 64;
    const int colBase = blockIdx.x * 64;

    float acc[4][4];
#pragma unroll
    for (int i = 0; i < 4; i++)
#pragma unroll
        for (int j = 0; j < 4; j++) acc[i][j] = 0.0f;

    for (int ks = 0; ks < K; ks += 32) {
#pragma unroll
        for (int l = 0; l < 2; l++) {
            int f = tid + l * 256;
            int row = f / 8;
            int kq = f % 8;
            int rg = rowBase + row;
            float4 v = make_float4(0.f, 0.f, 0.f, 0.f);
            if (rg < n) v = *(const float4*)(A + (size_t)rg * K + ks + kq * 4);
            As[kq * 4 + 0][row] = v.x;
            As[kq * 4 + 1][row] = v.y;
            As[kq * 4 + 2][row] = v.z;
            As[kq * 4 + 3][row] = v.w;
        }
#pragma unroll
        for (int l = 0; l < 2; l++) {
            int f = tid + l * 256;
            int k = f / 16;
            int cq = f % 16;
            float4 v = *(const float4*)(W + (size_t)(ks + k) * NOUT + colBase + cq * 4);
            *(float4*)&Bs[k][cq * 4] = v;
        }
        __syncthreads();

#pragma unroll
        for (int k = 0; k < 32; k++) {
            float4 a4 = *(const float4*)&As[k][ty * 4];
            float4 b4 = *(const float4*)&Bs[k][tx * 4];
            float a[4] = {a4.x, a4.y, a4.z, a4.w};
            float b[4] = {b4.x, b4.y, b4.z, b4.w};
#pragma unroll
            for (int i = 0; i < 4; i++)
#pragma unroll
                for (int j = 0; j < 4; j++) acc[i][j] += a[i] * b[j];
        }
        __syncthreads();
    }

#pragma unroll
    for (int i = 0; i < 4; i++) {
        int row = rowBase + ty * 4 + i;
        if (row >= n) continue;
        float dv = SCALE ? g_dinv[row] : 1.0f;
#pragma unroll
        for (int j = 0; j < 4; j++) {
            int col = colBase + tx * 4 + j;
            float v = acc[i][j];
            if (BIAS) v += bias[col];
            if (RELU) v = fmaxf(v, 0.0f);
            if (SCALE) v *= dv;
            C[(size_t)row * NOUT + col] = v;
        }
    }
}

// ---------------------------------------------------------------------------
extern "C" void kernel_launch(void* const* d_in, const int* in_sizes, int n_in,
                              void* d_out, int out_size) {
    const float* x   = (const float*)d_in[0];
    const int*   ei  = (const int*)d_in[1];     // int32 node ids
    const float* W1  = (const float*)d_in[2];
    const float* b1  = (const float*)d_in[3];
    const float* W2  = (const float*)d_in[4];
    const float* b2  = (const float*)d_in[5];
    const float* W3  = (const float*)d_in[6];
    const float* b3  = (const float*)d_in[7];
    float* out = (float*)d_out;

    const int N = in_sizes[0] / 64;
    const int E = in_sizes[1] / 2;
    const int NB = (N + SCAN_BS - 1) / SCAN_BS;

    const int T = 256;
    auto blk = [&](long long w) { return (int)((w + T - 1) / T); };

    // ---- CSR build + norms ----
    cnt_zero_kernel<<<blk(N), T>>>(N);
    cnt_count_kernel<<<blk(E), T>>>(ei, E);
    dinv_kernel<<<blk(N), T>>>(N);
    scan1_kernel<<<NB, SCAN_BS>>>(N);
    scan2_kernel<<<1, 32>>>(NB);
    scan3_kernel<<<blk(N), T>>>(N);
    cursor_init_kernel<<<blk(N), T>>>(N);
    csr_fill_kernel<<<blk(E), T>>>(ei, E);

    const int GT = 256;                         // gather: 8 warps/block
    const int gblk = (N + 7) / 8;

    // ---- Layer 1: xs = x*dinv (buf1); g1 = dinv*gather(xs) (buf2);
    //      h1s = relu(g1 W1 + b1)*dinv (buf1)
    scale_x_kernel<<<blk((long long)N * 16), T>>>(x, N);
    gather_kernel<64, 1, 2, false><<<gblk, GT>>>(nullptr, nullptr, nullptr, N);
    {
        dim3 grid(2, (N + 63) / 64);
        gemm_kernel<64, 128, true, true, true, 2, 1><<<grid, 256>>>(nullptr, W1, b1, nullptr, N);
    }

    // ---- Layer 2: g2 = dinv*gather(h1s) (buf2); h2s = relu(g2 W2 + b2)*dinv (buf1)
    gather_kernel<128, 1, 2, false><<<gblk, GT>>>(nullptr, nullptr, nullptr, N);
    {
        dim3 grid(2, (N + 63) / 64);
        gemm_kernel<128, 128, true, true, true, 2, 1><<<grid, 256>>>(nullptr, W2, b2, nullptr, N);
    }

    // ---- Layer 3: ps = h2s W3 (buf2); out = dinv*gather(ps) + b3
    {
        dim3 grid(1, (N + 63) / 64);
        gemm_kernel<128, 64, false, false, false, 1, 2><<<grid, 256>>>(nullptr, W3, nullptr, nullptr, N);
    }
    gather_kernel<64, 2, 0, true><<<gblk, GT>>>(nullptr, out, b3, N);
}

// round 6
// speedup vs baseline: 3.6211x; 1.2915x over previous
#include <cuda_runtime.h>

// ---------------------------------------------------------------------------
// GCN, 3 layers, A = D^-1/2 (Adj+I) D^-1/2.
// Pull aggregation over per-call CSR (no float atomics); dinv[src] pre-scale
// fused into GEMM epilogue, dinv[dst] post-scale fused into gather.
// GEMMs on the tensor pipe: tf32 mma.sync.m16n8k8, fp32 accumulate.
// ---------------------------------------------------------------------------

#define NODES 100000
#define EDGES 1600000
#define SCAN_BS 1024

__device__ __align__(16) int   g_cnt   [NODES];
__device__ __align__(16) int   g_rowptr[NODES + 1];
__device__ __align__(16) int   g_cursor[NODES];
__device__ __align__(16) int   g_blocksum[(NODES + SCAN_BS - 1) / SCAN_BS + 1];
__device__ __align__(16) float g_dinv  [NODES];
__device__ __align__(16) int   g_col   [EDGES];
__device__ __align__(16) float g_buf1[(size_t)NODES * 128];
__device__ __align__(16) float g_buf2[(size_t)NODES * 128];

template <int SEL>
__device__ __forceinline__ const float* cbuf(const float* ext) {
    if constexpr (SEL == 1) return g_buf1;
    else if constexpr (SEL == 2) return g_buf2;
    else return ext;
}
template <int SEL>
__device__ __forceinline__ float* mbuf(float* ext) {
    if constexpr (SEL == 1) return g_buf1;
    else if constexpr (SEL == 2) return g_buf2;
    else return ext;
}

__device__ __forceinline__ unsigned f2tf32(float f) {
    unsigned r;
    asm("cvt.rna.tf32.f32 %0, %1;" : "=r"(r) : "f"(f));
    return r;
}

// --------------------------- CSR construction ------------------------------
__global__ void cnt_zero_kernel(int n) {
    int i = blockIdx.x * blockDim.x + threadIdx.x;
    if (i < n) g_cnt[i] = 0;
}

__global__ void cnt_count_kernel(const int* __restrict__ ei, int e) {
    int i = blockIdx.x * blockDim.x + threadIdx.x;
    if (i < e) atomicAdd(&g_cnt[ei[e + i]], 1);
}

// Inclusive scan of g_cnt into g_rowptr[1..n] (+ per-block sums) and dinv.
__global__ void scan1_kernel(int n) {
    __shared__ int sh[SCAN_BS];
    int i = blockIdx.x * SCAN_BS + threadIdx.x;
    int v = (i < n) ? g_cnt[i] : 0;
    if (i < n) g_dinv[i] = rsqrtf((float)(v + 1));   // +1 self-loop
    sh[threadIdx.x] = v;
    __syncthreads();
#pragma unroll
    for (int off = 1; off < SCAN_BS; off <<= 1) {
        int t = (threadIdx.x >= off) ? sh[threadIdx.x - off] : 0;
        __syncthreads();
        sh[threadIdx.x] += t;
        __syncthreads();
    }
    if (i < n) g_rowptr[i + 1] = sh[threadIdx.x];
    if (threadIdx.x == SCAN_BS - 1) g_blocksum[blockIdx.x] = sh[threadIdx.x];
}

__global__ void scan2_kernel(int nb) {
    if (threadIdx.x == 0 && blockIdx.x == 0) {
        int run = 0;
        for (int b = 0; b < nb; b++) { int v = g_blocksum[b]; g_blocksum[b] = run; run += v; }
    }
}

__global__ void scan3_kernel(int n) {  // finalize rowptr + init cursors
    int i = blockIdx.x * blockDim.x + threadIdx.x;
    if (i < n) {
        int v = g_rowptr[i + 1] + g_blocksum[i / SCAN_BS];
        g_rowptr[i + 1] = v;
        if (i + 1 < n) g_cursor[i + 1] = v;
    }
    if (i == 0) { g_rowptr[0] = 0; g_cursor[0] = 0; }
}

__global__ void csr_fill_kernel(const int* __restrict__ ei, int e) {
    int i = blockIdx.x * blockDim.x + threadIdx.x;
    if (i < e) {
        int s = ei[i];
        int d = ei[e + i];
        int pos = atomicAdd(&g_cursor[d], 1);
        g_col[pos] = s;
    }
}

// --------------------------- feature kernels -------------------------------
__global__ void scale_x_kernel(const float* __restrict__ x, int n) {
    int t = blockIdx.x * blockDim.x + threadIdx.x;
    if (t >= n * 16) return;
    int i = t / 16, q = t % 16;
    float dv = g_dinv[i];
    float4 v = *(const float4*)(x + (size_t)i * 64 + q * 4);
    v.x *= dv; v.y *= dv; v.z *= dv; v.w *= dv;
    *(float4*)(g_buf1 + (size_t)i * 64 + q * 4) = v;
}

// Pull aggregation: one warp per node, lanes own feature slices.
template <int F, int HSEL, int OSEL, bool BIAS>
__global__ void gather_kernel(const float* h_ext, float* out_ext,
                              const float* __restrict__ bias, int n) {
    const float* __restrict__ hs = cbuf<HSEL>(h_ext);
    float* __restrict__ out = mbuf<OSEL>(out_ext);
    int warp = (blockIdx.x * blockDim.x + threadIdx.x) >> 5;
    int lane = threadIdx.x & 31;
    if (warp >= n) return;
    int beg = g_rowptr[warp], end = g_rowptr[warp + 1];

    if constexpr (F == 64) {
        float2 acc = *(const float2*)(hs + (size_t)warp * 64 + lane * 2);
        for (int base = beg; base < end; base += 32) {
            int e = base + lane;
            int c = (e < end) ? g_col[e] : 0;
            int m = min(32, end - base);
            for (int j = 0; j < m; j++) {
                int s = __shfl_sync(0xffffffffu, c, j);
                float2 v = *(const float2*)(hs + (size_t)s * 64 + lane * 2);
                acc.x += v.x; acc.y += v.y;
            }
        }
        float dv = g_dinv[warp];
        acc.x *= dv; acc.y *= dv;
        if constexpr (BIAS) { acc.x += bias[lane * 2]; acc.y += bias[lane * 2 + 1]; }
        *(float2*)(out + (size_t)warp * 64 + lane * 2) = acc;
    } else {
        float4 acc = *(const float4*)(hs + (size_t)warp * 128 + lane * 4);
        for (int base = beg; base < end; base += 32) {
            int e = base + lane;
            int c = (e < end) ? g_col[e] : 0;
            int m = min(32, end - base);
            for (int j = 0; j < m; j++) {
                int s = __shfl_sync(0xffffffffu, c, j);
                float4 v = *(const float4*)(hs + (size_t)s * 128 + lane * 4);
                acc.x += v.x; acc.y += v.y; acc.z += v.z; acc.w += v.w;
            }
        }
        float dv = g_dinv[warp];
        acc.x *= dv; acc.y *= dv; acc.z *= dv; acc.w *= dv;
        *(float4*)(out + (size_t)warp * 128 + lane * 4) = acc;
    }
}

// ---------------------------------------------------------------------------
// TF32 tensor-core GEMM: C[n,NOUT] = A[n,K] @ W[K,NOUT] (+bias)(+relu)(*dinv)
// Block tile 128x64, 256 threads (8 warps, 4x2), warp tile 32x32
// (2x4 m16n8k8 atoms), BK=32 staged in smem as tf32 bits.
// ---------------------------------------------------------------------------
template <int K, int NOUT, bool RELU, bool BIAS, bool SCALE, int ASEL, int CSEL>
__global__ void gemm_tf32_kernel(const float* A_ext,
                                 const float* __restrict__ W,
                                 const float* __restrict__ bias,
                                 float* C_ext, int n) {
    const float* __restrict__ A = cbuf<ASEL>(A_ext);
    float* __restrict__ C = mbuf<CSEL>(C_ext);

    __shared__ unsigned As[32][132];   // [k][m], pad 4 -> frag loads conflict-free
    __shared__ unsigned Bs[32][68];    // [k][n], pad 4

    const int tid = threadIdx.x;
    const int wid = tid >> 5;
    const int lane = tid & 31;
    const int warp_m = wid & 3;        // 0..3  (rows)
    const int warp_n = wid >> 2;       // 0..1  (cols)
    const int lk = lane & 3;
    const int lg = lane >> 2;          // groupID
    const int rowBase = blockIdx.y * 128;
    const int colBase = blockIdx.x * 64;

    float acc[2][4][4];
#pragma unroll
    for (int mi = 0; mi < 2; mi++)
#pragma unroll
        for (int ni = 0; ni < 4; ni++)
#pragma unroll
            for (int r = 0; r < 4; r++) acc[mi][ni][r] = 0.0f;

    for (int ks = 0; ks < K; ks += 32) {
        // Stage A: 128 rows x 32 k = 1024 float4, 4 per thread, transposed + tf32
#pragma unroll
        for (int l = 0; l < 4; l++) {
            int f = tid + l * 256;
            int row = f >> 3;            // 8 float4 per row
            int kq = f & 7;
            int rg = rowBase + row;
            float4 v = make_float4(0.f, 0.f, 0.f, 0.f);
            if (rg < n) v = *(const float4*)(A + (size_t)rg * K + ks + kq * 4);
            As[kq * 4 + 0][row] = f2tf32(v.x);
            As[kq * 4 + 1][row] = f2tf32(v.y);
            As[kq * 4 + 2][row] = f2tf32(v.z);
            As[kq * 4 + 3][row] = f2tf32(v.w);
        }
        // Stage B: 32 k x 64 n = 512 float4, 2 per thread, tf32
#pragma unroll
        for (int l = 0; l < 2; l++) {
            int f = tid + l * 256;
            int k = f >> 4;              // 16 float4 per row
            int cq = f & 15;
            float4 v = *(const float4*)(W + (size_t)(ks + k) * NOUT + colBase + cq * 4);
            Bs[k][cq * 4 + 0] = f2tf32(v.x);
            Bs[k][cq * 4 + 1] = f2tf32(v.y);
            Bs[k][cq * 4 + 2] = f2tf32(v.z);
            Bs[k][cq * 4 + 3] = f2tf32(v.w);
        }
        __syncthreads();

#pragma unroll
        for (int ka = 0; ka < 4; ka++) {
            const int kb = ka * 8;
            unsigned a[2][4], b[4][2];
#pragma unroll
            for (int mi = 0; mi < 2; mi++) {
                int m0 = warp_m * 32 + mi * 16;
                a[mi][0] = As[kb + lk    ][m0 + lg    ];
                a[mi][1] = As[kb + lk    ][m0 + lg + 8];
                a[mi][2] = As[kb + lk + 4][m0 + lg    ];
                a[mi][3] = As[kb + lk + 4][m0 + lg + 8];
            }
#pragma unroll
            for (int ni = 0; ni < 4; ni++) {
                int n0 = warp_n * 32 + ni * 8;
                b[ni][0] = Bs[kb + lk    ][n0 + lg];
                b[ni][1] = Bs[kb + lk + 4][n0 + lg];
            }
#pragma unroll
            for (int mi = 0; mi < 2; mi++)
#pragma unroll
                for (int ni = 0; ni < 4; ni++) {
                    asm volatile(
                        "mma.sync.aligned.m16n8k8.row.col.f32.tf32.tf32.f32 "
                        "{%0,%1,%2,%3}, {%4,%5,%6,%7}, {%8,%9}, {%0,%1,%2,%3};"
                        : "+f"(acc[mi][ni][0]), "+f"(acc[mi][ni][1]),
                          "+f"(acc[mi][ni][2]), "+f"(acc[mi][ni][3])
                        : "r"(a[mi][0]), "r"(a[mi][1]), "r"(a[mi][2]), "r"(a[mi][3]),
                          "r"(b[ni][0]), "r"(b[ni][1]));
                }
        }
        __syncthreads();
    }

    // Epilogue: c0,c1 -> (row, col..col+1), c2,c3 -> (row+8, ...)
#pragma unroll
    for (int mi = 0; mi < 2; mi++) {
        int row0 = rowBase + warp_m * 32 + mi * 16 + lg;
        int row1 = row0 + 8;
        float dv0 = 1.0f, dv1 = 1.0f;
        if (SCALE) {
            if (row0 < n) dv0 = g_dinv[row0];
            if (row1 < n) dv1 = g_dinv[row1];
        }
#pragma unroll
        for (int ni = 0; ni < 4; ni++) {
            int col = colBase + warp_n * 32 + ni * 8 + lk * 2;
            float bx = 0.f, by = 0.f;
            if (BIAS) { bx = bias[col]; by = bias[col + 1]; }
            float v0 = acc[mi][ni][0] + bx;
            float v1 = acc[mi][ni][1] + by;
            float v2 = acc[mi][ni][2] + bx;
            float v3 = acc[mi][ni][3] + by;
            if (RELU) {
                v0 = fmaxf(v0, 0.f); v1 = fmaxf(v1, 0.f);
                v2 = fmaxf(v2, 0.f); v3 = fmaxf(v3, 0.f);
            }
            if (row0 < n) *(float2*)(C + (size_t)row0 * NOUT + col) = make_float2(v0 * dv0, v1 * dv0);
            if (row1 < n) *(float2*)(C + (size_t)row1 * NOUT + col) = make_float2(v2 * dv1, v3 * dv1);
        }
    }
}

// ---------------------------------------------------------------------------
extern "C" void kernel_launch(void* const* d_in, const int* in_sizes, int n_in,
                              void* d_out, int out_size) {
    const float* x   = (const float*)d_in[0];
    const int*   ei  = (const int*)d_in[1];
    const float* W1  = (const float*)d_in[2];
    const float* b1  = (const float*)d_in[3];
    const float* W2  = (const float*)d_in[4];
    const float* b2  = (const float*)d_in[5];
    const float* W3  = (const float*)d_in[6];
    const float* b3  = (const float*)d_in[7];
    float* out = (float*)d_out;

    const int N = in_sizes[0] / 64;
    const int E = in_sizes[1] / 2;
    const int NB = (N + SCAN_BS - 1) / SCAN_BS;

    const int T = 256;
    auto blk = [&](long long w) { return (int)((w + T - 1) / T); };

    // ---- CSR build + norms ----
    cnt_zero_kernel<<<blk(N), T>>>(N);
    cnt_count_kernel<<<blk(E), T>>>(ei, E);
    scan1_kernel<<<NB, SCAN_BS>>>(N);
    scan2_kernel<<<1, 32>>>(NB);
    scan3_kernel<<<blk(N), T>>>(N);
    csr_fill_kernel<<<blk(E), T>>>(ei, E);

    const int GT = 256;
    const int gblk = (N + 7) / 8;
    const int gy = (N + 127) / 128;

    // ---- Layer 1 ----
    scale_x_kernel<<<blk((long long)N * 16), T>>>(x, N);
    gather_kernel<64, 1, 2, false><<<gblk, GT>>>(nullptr, nullptr, nullptr, N);
    gemm_tf32_kernel<64, 128, true, true, true, 2, 1><<<dim3(2, gy), 256>>>(nullptr, W1, b1, nullptr, N);

    // ---- Layer 2 ----
    gather_kernel<128, 1, 2, false><<<gblk, GT>>>(nullptr, nullptr, nullptr, N);
    gemm_tf32_kernel<128, 128, true, true, true, 2, 1><<<dim3(2, gy), 256>>>(nullptr, W2, b2, nullptr, N);

    // ---- Layer 3 ----
    gemm_tf32_kernel<128, 64, false, false, false, 1, 2><<<dim3(1, gy), 256>>>(nullptr, W3, nullptr, nullptr, N);
    gather_kernel<64, 2, 0, true><<<gblk, GT>>>(nullptr, out, b3, N);
}